// round 10
// baseline (speedup 1.0000x reference)
#include <cuda_runtime.h>
#include <cuda_fp16.h>
#include <math.h>

#define LDIM 1024
#define BDIM 4
#define STEPS 16
#define RPB 4  // rows per block in step kernel

// Scratch (allocation-free rule: __device__ globals)
__device__ __half        g_Ush[(size_t)BDIM * LDIM * LDIM];   // Us = 0.5(x+x^T)-s, fp16
__device__ unsigned char g_M8[(size_t)BDIM * LDIM * LDIM];    // mask as u8
__device__ float         g_Ahat[(size_t)BDIM * LDIM * LDIM];
__device__ float g_rs[BDIM * LDIM];
__device__ float g_cs[BDIM * LDIM];
__device__ float g_Lm[BDIM * LDIM];
__device__ float g_c[BDIM * LDIM];

// ---------------------------------------------------------------------------
// Zero row/col accumulators (start of every replay; makes replay idempotent)
// ---------------------------------------------------------------------------
__global__ void zero_kernel() {
    int i = blockIdx.x * blockDim.x + threadIdx.x;
    if (i < BDIM * LDIM) { g_rs[i] = 0.f; g_cs[i] = 0.f; }
}

// ---------------------------------------------------------------------------
// Init: Us(fp16) = 0.5*(x + x^T) - s ; M8 = (u8)M ; accumulate rs/cs of x.*M
// grid (32, 32, 4), block (32, 8); 32x32 tiles, 4 rows/thread
// (identical to R7's init_kernel, which passed)
// ---------------------------------------------------------------------------
__global__ void init_kernel(const float* __restrict__ x,
                            const float* __restrict__ M,
                            const float* __restrict__ s_p) {
    __shared__ float t2[32][33];
    int b = blockIdx.z;
    int tx = blockIdx.x, ty = blockIdx.y;
    int c = threadIdx.x;
    int r0 = threadIdx.y * 4;
    float s = s_p[0];
    const float* xb = x + (size_t)b * LDIM * LDIM;
    const float* mb = M + (size_t)b * LDIM * LDIM;
    size_t bbase = (size_t)b * LDIM * LDIM;

    // partner tile: x[b, tx*32 + r, ty*32 + c]
#pragma unroll
    for (int k = 0; k < 4; k++) {
        int r = r0 + k;
        t2[r][c] = xb[(size_t)(tx * 32 + r) * LDIM + ty * 32 + c];
    }
    __syncthreads();

    float colsum = 0.f;
#pragma unroll
    for (int k = 0; k < 4; k++) {
        int r = r0 + k;
        int gi = ty * 32 + r;
        int gj = tx * 32 + c;
        size_t idx = (size_t)gi * LDIM + gj;
        float xv = xb[idx];
        float mv = mb[idx];
        float us = 0.5f * (xv + t2[c][r]) - s;
        g_Ush[bbase + idx] = __float2half(us);
        g_M8[bbase + idx] = (unsigned char)(mv != 0.0f ? 1 : 0);
        float am = xv * mv;
        float rp = am;
#pragma unroll
        for (int o = 16; o > 0; o >>= 1) rp += __shfl_down_sync(0xffffffffu, rp, o);
        if (c == 0) atomicAdd(&g_rs[b * LDIM + gi], rp);
        colsum += am;
    }
    atomicAdd(&g_cs[b * LDIM + tx * 32 + c], colsum);
}

// ---------------------------------------------------------------------------
// Lm / c update (identical to R7's, verified).
// init_flag=1: Lm = w*relu(r). else Lm += belt*lr_belt^t*relu(r)
// r = 0.5*(rs+cs) - 1 ; c = Lm * sign(r) ; zero rs/cs for next step.
// ---------------------------------------------------------------------------
__global__ void lm_kernel(const float* __restrict__ w_p,
                          const float* __restrict__ belt_p,
                          const float* __restrict__ lrb_p,
                          int t, int init_flag) {
    int i = blockIdx.x * blockDim.x + threadIdx.x;
    if (i >= BDIM * LDIM) return;
    float r = 0.5f * (g_rs[i] + g_cs[i]) - 1.0f;
    float pr = fmaxf(r, 0.f);
    float lm;
    if (init_flag) {
        lm = w_p[0] * pr;
    } else {
        lm = g_Lm[i] + belt_p[0] * powf(lrb_p[0], (float)t) * pr;
    }
    g_Lm[i] = lm;
    float sgn = (r > 0.f) ? 1.f : ((r < 0.f) ? -1.f : 0.f);
    g_c[i] = lm * sgn;
    g_rs[i] = 0.f;
    g_cs[i] = 0.f;
}

// ---------------------------------------------------------------------------
// Step kernel: R7's exact loop body (in-loop shuffle row reduction, fp32 rho
// straight from the input pointer), RPB=4 for 2x grid / higher occupancy.
// grid (LDIM/RPB, BDIM), block 256. Block covers RPB full rows.
// Thread tid handles cols [4*tid, 4*tid+4).
// ---------------------------------------------------------------------------
__global__ void __launch_bounds__(256)
step_kernel(const float* __restrict__ x,
            const float* __restrict__ rho,
            const float* __restrict__ alpha_p,
            const float* __restrict__ lra_p,
            int t, int use_x) {
    int b = blockIdx.y;
    int row0 = blockIdx.x * RPB;
    int tid = threadIdx.x;
    int wid = tid >> 5, lane = tid & 31;
    int j0 = tid * 4;

    const float* Ain = use_x ? x : (const float*)g_Ahat;
    float* Aout = g_Ahat;

    float at = alpha_p[0] * powf(lra_p[0], (float)t);

    size_t baseB = (size_t)b * LDIM * LDIM;
    float4 cj = *(const float4*)&g_c[b * LDIM + j0];
    float ca0 = 0.f, ca1 = 0.f, ca2 = 0.f, ca3 = 0.f;

    __shared__ float srow[8][RPB];

#pragma unroll
    for (int r = 0; r < RPB; r++) {
        int row = row0 + r;
        size_t base = baseB + (size_t)row * LDIM + j0;
        float4 ah = *(const float4*)(Ain + base);
        unsigned int m_c = *(const unsigned int*)(g_M8 + base);
        uint2 uu = *(const uint2*)(g_Ush + base);
        float4 rp = *(const float4*)(rho + (size_t)row * LDIM + j0);
        float ci = g_c[b * LDIM + row];

        float2 us01 = __half22float2(*reinterpret_cast<__half2*>(&uu.x));
        float2 us23 = __half22float2(*reinterpret_cast<__half2*>(&uu.y));
        float m0 = (float)(m_c & 0xff), m1 = (float)((m_c >> 8) & 0xff);
        float m2 = (float)((m_c >> 16) & 0xff), m3 = (float)(m_c >> 24);

        float rowp = 0.f;
        float4 ov;
        {
            float g = us01.x - ci - cj.x;
            float v = ah.x + at * ah.x * m0 * g;
            float sv = fminf(fmaxf(fabsf(v) - rp.x * at, 0.f), 1.f);
            ov.x = sv; float am = sv * m0; rowp += am; ca0 += am;
        }
        {
            float g = us01.y - ci - cj.y;
            float v = ah.y + at * ah.y * m1 * g;
            float sv = fminf(fmaxf(fabsf(v) - rp.y * at, 0.f), 1.f);
            ov.y = sv; float am = sv * m1; rowp += am; ca1 += am;
        }
        {
            float g = us23.x - ci - cj.z;
            float v = ah.z + at * ah.z * m2 * g;
            float sv = fminf(fmaxf(fabsf(v) - rp.z * at, 0.f), 1.f);
            ov.z = sv; float am = sv * m2; rowp += am; ca2 += am;
        }
        {
            float g = us23.y - ci - cj.w;
            float v = ah.w + at * ah.w * m3 * g;
            float sv = fminf(fmaxf(fabsf(v) - rp.w * at, 0.f), 1.f);
            ov.w = sv; float am = sv * m3; rowp += am; ca3 += am;
        }
        *(float4*)(Aout + base) = ov;

#pragma unroll
        for (int o = 16; o > 0; o >>= 1) rowp += __shfl_down_sync(0xffffffffu, rowp, o);
        if (lane == 0) srow[wid][r] = rowp;
    }
    __syncthreads();
    if (tid < RPB) {
        float s = 0.f;
#pragma unroll
        for (int w = 0; w < 8; w++) s += srow[w][tid];
        g_rs[b * LDIM + row0 + tid] = s;  // block covers full row: direct store
    }
    atomicAdd(&g_cs[b * LDIM + j0 + 0], ca0);
    atomicAdd(&g_cs[b * LDIM + j0 + 1], ca1);
    atomicAdd(&g_cs[b * LDIM + j0 + 2], ca2);
    atomicAdd(&g_cs[b * LDIM + j0 + 3], ca3);
}

// ---------------------------------------------------------------------------
// Final: out = 0.5*(Ahat + Ahat^T) .* M   (tiled transpose, u8 mask)
// ---------------------------------------------------------------------------
__global__ void final_kernel(float* __restrict__ out) {
    __shared__ float t2[32][33];
    int b = blockIdx.z;
    int tx = blockIdx.x, ty = blockIdx.y;
    int c = threadIdx.x;
    int r0 = threadIdx.y * 4;
    const float* ab = g_Ahat + (size_t)b * LDIM * LDIM;
    const unsigned char* mb = g_M8 + (size_t)b * LDIM * LDIM;
    float* ob = out + (size_t)b * LDIM * LDIM;

#pragma unroll
    for (int k = 0; k < 4; k++) {
        int r = r0 + k;
        t2[r][c] = ab[(size_t)(tx * 32 + r) * LDIM + ty * 32 + c];
    }
    __syncthreads();
#pragma unroll
    for (int k = 0; k < 4; k++) {
        int r = r0 + k;
        int gi = ty * 32 + r;
        int gj = tx * 32 + c;
        size_t idx = (size_t)gi * LDIM + gj;
        ob[idx] = 0.5f * (ab[idx] + t2[c][r]) * (float)mb[idx];
    }
}

// ---------------------------------------------------------------------------
extern "C" void kernel_launch(void* const* d_in, const int* in_sizes, int n_in,
                              void* d_out, int out_size) {
    const float* x     = (const float*)d_in[0];
    const float* M     = (const float*)d_in[1];
    const float* s_p   = (const float*)d_in[2];
    const float* w_p   = (const float*)d_in[3];
    const float* rho_p = (const float*)d_in[4];
    const float* alpha_p = (const float*)d_in[5];
    const float* belt_p  = (const float*)d_in[6];
    const float* lra_p   = (const float*)d_in[7];
    const float* lrb_p   = (const float*)d_in[8];
    float* out = (float*)d_out;

    // 1. zero accumulators
    zero_kernel<<<(BDIM * LDIM + 255) / 256, 256>>>();

    // 2. init: Us(fp16), M8, rs/cs of x.*M
    dim3 tgrid(LDIM / 32, LDIM / 32, BDIM);
    dim3 tblk(32, 8);
    init_kernel<<<tgrid, tblk>>>(x, M, s_p);

    // 3. Lm0, c0
    lm_kernel<<<(BDIM * LDIM + 255) / 256, 256>>>(w_p, belt_p, lrb_p, 0, 1);

    // 4. main loop (skip lm on the last step: Lm/c unused afterward)
    dim3 sgrid(LDIM / RPB, BDIM);
    for (int t = 0; t < STEPS; t++) {
        step_kernel<<<sgrid, 256>>>(x, rho_p, alpha_p, lra_p, t, t == 0 ? 1 : 0);
        if (t < STEPS - 1)
            lm_kernel<<<(BDIM * LDIM + 255) / 256, 256>>>(w_p, belt_p, lrb_p, t, 0);
    }

    // 5. output symmetrize
    final_kernel<<<tgrid, tblk>>>(out);
}

// round 11
// speedup vs baseline: 1.8426x; 1.8426x over previous
#include <cuda_runtime.h>
#include <cuda_fp16.h>
#include <math.h>

#define LDIM 1024
#define BDIM 4
#define STEPS 16
#define RPB 8  // rows per block in step kernel

// Scratch (allocation-free rule: __device__ globals)
__device__ __half        g_Ush[(size_t)BDIM * LDIM * LDIM];   // Us = 0.5(x+x^T)-s, fp16
__device__ unsigned char g_M8[(size_t)BDIM * LDIM * LDIM];    // mask as u8
__device__ float         g_Ahat[(size_t)BDIM * LDIM * LDIM];
// Step-indexed sum buffers: S[t] = row/col sums of A entering step t (S[0] from init)
__device__ float g_Srs[STEPS + 1][BDIM * LDIM];
__device__ float g_Scs[STEPS + 1][BDIM * LDIM];
__device__ float g_LmBuf[2][BDIM * LDIM];

// ---------------------------------------------------------------------------
// Zero ALL step-sum buffers (start of every replay; makes replay idempotent)
// ---------------------------------------------------------------------------
__global__ void zero_kernel() {
    int n = (STEPS + 1) * BDIM * LDIM;
    int i = blockIdx.x * blockDim.x + threadIdx.x;
    if (i < n) {
        ((float*)g_Srs)[i] = 0.f;
        ((float*)g_Scs)[i] = 0.f;
    }
}

// ---------------------------------------------------------------------------
// Init: Us(fp16) = 0.5*(x + x^T) - s ; M8 = (u8)M ; accumulate S[0] of x.*M
// grid (32, 32, 4), block (32, 8); 32x32 tiles, 4 rows/thread
// (R7's init_kernel with sums redirected to S[0])
// ---------------------------------------------------------------------------
__global__ void init_kernel(const float* __restrict__ x,
                            const float* __restrict__ M,
                            const float* __restrict__ s_p) {
    __shared__ float t2[32][33];
    int b = blockIdx.z;
    int tx = blockIdx.x, ty = blockIdx.y;
    int c = threadIdx.x;
    int r0 = threadIdx.y * 4;
    float s = s_p[0];
    const float* xb = x + (size_t)b * LDIM * LDIM;
    const float* mb = M + (size_t)b * LDIM * LDIM;
    size_t bbase = (size_t)b * LDIM * LDIM;

    // partner tile: x[b, tx*32 + r, ty*32 + c]
#pragma unroll
    for (int k = 0; k < 4; k++) {
        int r = r0 + k;
        t2[r][c] = xb[(size_t)(tx * 32 + r) * LDIM + ty * 32 + c];
    }
    __syncthreads();

    float colsum = 0.f;
#pragma unroll
    for (int k = 0; k < 4; k++) {
        int r = r0 + k;
        int gi = ty * 32 + r;
        int gj = tx * 32 + c;
        size_t idx = (size_t)gi * LDIM + gj;
        float xv = xb[idx];
        float mv = mb[idx];
        float us = 0.5f * (xv + t2[c][r]) - s;
        g_Ush[bbase + idx] = __float2half(us);
        g_M8[bbase + idx] = (unsigned char)(mv != 0.0f ? 1 : 0);
        float am = xv * mv;
        float rp = am;
#pragma unroll
        for (int o = 16; o > 0; o >>= 1) rp += __shfl_down_sync(0xffffffffu, rp, o);
        if (c == 0) atomicAdd(&g_Srs[0][b * LDIM + gi], rp);
        colsum += am;
    }
    atomicAdd(&g_Scs[0][b * LDIM + tx * 32 + c], colsum);
}

// ---------------------------------------------------------------------------
// Step kernel: fused Lm/c prologue (from S[t]) + R7's exact loop body.
// grid (LDIM/RPB, BDIM), block 256. Block covers RPB full rows.
// Thread tid handles cols [4*tid, 4*tid+4).
// Lm semantics: step t uses Lm_t where Lm_0 = w*relu(r_0),
//   Lm_t = Lm_{t-1} + belt*lrb^(t-1)*relu(r_t), r_t from S[t].
// ---------------------------------------------------------------------------
__global__ void __launch_bounds__(256)
step_kernel(const float* __restrict__ x,
            const float* __restrict__ rho,
            const float* __restrict__ w_p,
            const float* __restrict__ alpha_p,
            const float* __restrict__ belt_p,
            const float* __restrict__ lra_p,
            const float* __restrict__ lrb_p,
            int t, int use_x) {
    int b = blockIdx.y;
    int row0 = blockIdx.x * RPB;
    int tid = threadIdx.x;
    int wid = tid >> 5, lane = tid & 31;
    int j0 = tid * 4;
    int bL = b * LDIM;

    __shared__ float c_sh[LDIM];
    __shared__ float srow[8][RPB];

    // ---- prologue: Lm / c from S[t] (every block, redundant but cheap) ----
    {
        float4 rs = *(const float4*)&g_Srs[t][bL + j0];
        float4 cs = *(const float4*)&g_Scs[t][bL + j0];
        float4 lmp = make_float4(0.f, 0.f, 0.f, 0.f);
        if (t > 0) lmp = *(const float4*)&g_LmBuf[(t - 1) & 1][bL + j0];
        float wv = w_p[0];
        float bt = belt_p[0] * powf(lrb_p[0], (float)(t - 1));
        float4 lm;
#pragma unroll
        for (int k = 0; k < 4; k++) {
            float r = 0.5f * (((const float*)&rs)[k] + ((const float*)&cs)[k]) - 1.0f;
            float pr = fmaxf(r, 0.f);
            float l = (t == 0) ? (wv * pr) : (((const float*)&lmp)[k] + bt * pr);
            float sgn = (r > 0.f) ? 1.f : ((r < 0.f) ? -1.f : 0.f);
            ((float*)&lm)[k] = l;
            c_sh[j0 + k] = l * sgn;
        }
        if (blockIdx.x == 0) *(float4*)&g_LmBuf[t & 1][bL + j0] = lm;
    }
    __syncthreads();

    const float* Ain = use_x ? x : (const float*)g_Ahat;
    float* Aout = g_Ahat;

    float at = alpha_p[0] * powf(lra_p[0], (float)t);

    size_t baseB = (size_t)b * LDIM * LDIM;
    float4 cj = *(const float4*)&c_sh[j0];
    float ca0 = 0.f, ca1 = 0.f, ca2 = 0.f, ca3 = 0.f;

#pragma unroll
    for (int r = 0; r < RPB; r++) {
        int row = row0 + r;
        size_t base = baseB + (size_t)row * LDIM + j0;
        float4 ah = *(const float4*)(Ain + base);
        unsigned int m_c = *(const unsigned int*)(g_M8 + base);
        uint2 uu = *(const uint2*)(g_Ush + base);
        float4 rp = *(const float4*)(rho + (size_t)row * LDIM + j0);
        float ci = c_sh[row];

        float2 us01 = __half22float2(*reinterpret_cast<__half2*>(&uu.x));
        float2 us23 = __half22float2(*reinterpret_cast<__half2*>(&uu.y));
        float m0 = (float)(m_c & 0xff), m1 = (float)((m_c >> 8) & 0xff);
        float m2 = (float)((m_c >> 16) & 0xff), m3 = (float)(m_c >> 24);

        float rowp = 0.f;
        float4 ov;
        {
            float g = us01.x - ci - cj.x;
            float v = ah.x + at * ah.x * m0 * g;
            float sv = fminf(fmaxf(fabsf(v) - rp.x * at, 0.f), 1.f);
            ov.x = sv; float am = sv * m0; rowp += am; ca0 += am;
        }
        {
            float g = us01.y - ci - cj.y;
            float v = ah.y + at * ah.y * m1 * g;
            float sv = fminf(fmaxf(fabsf(v) - rp.y * at, 0.f), 1.f);
            ov.y = sv; float am = sv * m1; rowp += am; ca1 += am;
        }
        {
            float g = us23.x - ci - cj.z;
            float v = ah.z + at * ah.z * m2 * g;
            float sv = fminf(fmaxf(fabsf(v) - rp.z * at, 0.f), 1.f);
            ov.z = sv; float am = sv * m2; rowp += am; ca2 += am;
        }
        {
            float g = us23.y - ci - cj.w;
            float v = ah.w + at * ah.w * m3 * g;
            float sv = fminf(fmaxf(fabsf(v) - rp.w * at, 0.f), 1.f);
            ov.w = sv; float am = sv * m3; rowp += am; ca3 += am;
        }
        *(float4*)(Aout + base) = ov;

#pragma unroll
        for (int o = 16; o > 0; o >>= 1) rowp += __shfl_down_sync(0xffffffffu, rowp, o);
        if (lane == 0) srow[wid][r] = rowp;
    }
    __syncthreads();
    if (tid < RPB) {
        float s = 0.f;
#pragma unroll
        for (int w = 0; w < 8; w++) s += srow[w][tid];
        g_Srs[t + 1][bL + row0 + tid] = s;  // block covers full row: direct store
    }
    atomicAdd(&g_Scs[t + 1][bL + j0 + 0], ca0);
    atomicAdd(&g_Scs[t + 1][bL + j0 + 1], ca1);
    atomicAdd(&g_Scs[t + 1][bL + j0 + 2], ca2);
    atomicAdd(&g_Scs[t + 1][bL + j0 + 3], ca3);
}

// ---------------------------------------------------------------------------
// Final: out = 0.5*(Ahat + Ahat^T) .* M   (tiled transpose, u8 mask)
// ---------------------------------------------------------------------------
__global__ void final_kernel(float* __restrict__ out) {
    __shared__ float t2[32][33];
    int b = blockIdx.z;
    int tx = blockIdx.x, ty = blockIdx.y;
    int c = threadIdx.x;
    int r0 = threadIdx.y * 4;
    const float* ab = g_Ahat + (size_t)b * LDIM * LDIM;
    const unsigned char* mb = g_M8 + (size_t)b * LDIM * LDIM;
    float* ob = out + (size_t)b * LDIM * LDIM;

#pragma unroll
    for (int k = 0; k < 4; k++) {
        int r = r0 + k;
        t2[r][c] = ab[(size_t)(tx * 32 + r) * LDIM + ty * 32 + c];
    }
    __syncthreads();
#pragma unroll
    for (int k = 0; k < 4; k++) {
        int r = r0 + k;
        int gi = ty * 32 + r;
        int gj = tx * 32 + c;
        size_t idx = (size_t)gi * LDIM + gj;
        ob[idx] = 0.5f * (ab[idx] + t2[c][r]) * (float)mb[idx];
    }
}

// ---------------------------------------------------------------------------
extern "C" void kernel_launch(void* const* d_in, const int* in_sizes, int n_in,
                              void* d_out, int out_size) {
    const float* x     = (const float*)d_in[0];
    const float* M     = (const float*)d_in[1];
    const float* s_p   = (const float*)d_in[2];
    const float* w_p   = (const float*)d_in[3];
    const float* rho_p = (const float*)d_in[4];
    const float* alpha_p = (const float*)d_in[5];
    const float* belt_p  = (const float*)d_in[6];
    const float* lra_p   = (const float*)d_in[7];
    const float* lrb_p   = (const float*)d_in[8];
    float* out = (float*)d_out;

    // 1. zero all step-sum buffers
    int nz = (STEPS + 1) * BDIM * LDIM;
    zero_kernel<<<(nz + 255) / 256, 256>>>();

    // 2. init: Us(fp16), M8, S[0]
    dim3 tgrid(LDIM / 32, LDIM / 32, BDIM);
    dim3 tblk(32, 8);
    init_kernel<<<tgrid, tblk>>>(x, M, s_p);

    // 3. main loop (Lm/c fused into step prologue)
    dim3 sgrid(LDIM / RPB, BDIM);
    for (int t = 0; t < STEPS; t++) {
        step_kernel<<<sgrid, 256>>>(x, rho_p, w_p, alpha_p, belt_p, lra_p, lrb_p,
                                    t, t == 0 ? 1 : 0);
    }

    // 4. output symmetrize
    final_kernel<<<tgrid, tblk>>>(out);
}

// round 12
// speedup vs baseline: 1.8736x; 1.0168x over previous
#include <cuda_runtime.h>
#include <cuda_fp16.h>
#include <cuda_pipeline.h>
#include <math.h>

#define LDIM 1024
#define BDIM 4
#define STEPS 16
#define RPB 8   // rows per block in step kernel
#define NSTG 3  // cp.async pipeline stages (rows in flight = NSTG-1)

// Stage layout (bytes): A[1024]f32 | rho[1024]f32 | Us[1024]f16 | M[1024]u8
#define A_OFF 0
#define R_OFF 4096
#define U_OFF 8192
#define M_OFF 10240
#define STAGE_BYTES 11264

// Scratch (allocation-free rule: __device__ globals)
__device__ __half        g_Ush[(size_t)BDIM * LDIM * LDIM];   // Us = 0.5(x+x^T)-s, fp16
__device__ unsigned char g_M8[(size_t)BDIM * LDIM * LDIM];    // mask as u8
__device__ float         g_Ahat[(size_t)BDIM * LDIM * LDIM];
// Step-indexed sum buffers: S[t] = row/col sums of A entering step t (S[0] from init)
__device__ float g_Srs[STEPS + 1][BDIM * LDIM];
__device__ float g_Scs[STEPS + 1][BDIM * LDIM];
__device__ float g_LmBuf[2][BDIM * LDIM];

// ---------------------------------------------------------------------------
// Zero ALL step-sum buffers (start of every replay; makes replay idempotent)
// ---------------------------------------------------------------------------
__global__ void zero_kernel() {
    int n = (STEPS + 1) * BDIM * LDIM;
    int i = blockIdx.x * blockDim.x + threadIdx.x;
    if (i < n) {
        ((float*)g_Srs)[i] = 0.f;
        ((float*)g_Scs)[i] = 0.f;
    }
}

// ---------------------------------------------------------------------------
// Init: Us(fp16) = 0.5*(x + x^T) - s ; M8 = (u8)M ; accumulate S[0] of x.*M
// grid (32, 32, 4), block (32, 8); 32x32 tiles, 4 rows/thread
// ---------------------------------------------------------------------------
__global__ void init_kernel(const float* __restrict__ x,
                            const float* __restrict__ M,
                            const float* __restrict__ s_p) {
    __shared__ float t2[32][33];
    int b = blockIdx.z;
    int tx = blockIdx.x, ty = blockIdx.y;
    int c = threadIdx.x;
    int r0 = threadIdx.y * 4;
    float s = s_p[0];
    const float* xb = x + (size_t)b * LDIM * LDIM;
    const float* mb = M + (size_t)b * LDIM * LDIM;
    size_t bbase = (size_t)b * LDIM * LDIM;

    // partner tile: x[b, tx*32 + r, ty*32 + c]
#pragma unroll
    for (int k = 0; k < 4; k++) {
        int r = r0 + k;
        t2[r][c] = xb[(size_t)(tx * 32 + r) * LDIM + ty * 32 + c];
    }
    __syncthreads();

    float colsum = 0.f;
#pragma unroll
    for (int k = 0; k < 4; k++) {
        int r = r0 + k;
        int gi = ty * 32 + r;
        int gj = tx * 32 + c;
        size_t idx = (size_t)gi * LDIM + gj;
        float xv = xb[idx];
        float mv = mb[idx];
        float us = 0.5f * (xv + t2[c][r]) - s;
        g_Ush[bbase + idx] = __float2half(us);
        g_M8[bbase + idx] = (unsigned char)(mv != 0.0f ? 1 : 0);
        float am = xv * mv;
        float rp = am;
#pragma unroll
        for (int o = 16; o > 0; o >>= 1) rp += __shfl_down_sync(0xffffffffu, rp, o);
        if (c == 0) atomicAdd(&g_Srs[0][b * LDIM + gi], rp);
        colsum += am;
    }
    atomicAdd(&g_Scs[0][b * LDIM + tx * 32 + c], colsum);
}

// ---------------------------------------------------------------------------
// Step kernel: fused Lm/c prologue + cp.async-staged elementwise update.
// grid (LDIM/RPB, BDIM), block 256. Block covers RPB full rows.
// Thread tid handles cols [4*tid, 4*tid+4); each thread consumes only the
// smem bytes it copied, so the pipeline needs no block-level syncs.
// ---------------------------------------------------------------------------
__global__ void __launch_bounds__(256)
step_kernel(const float* __restrict__ x,
            const float* __restrict__ rho,
            const float* __restrict__ w_p,
            const float* __restrict__ alpha_p,
            const float* __restrict__ belt_p,
            const float* __restrict__ lra_p,
            const float* __restrict__ lrb_p,
            int t, int use_x) {
    int b = blockIdx.y;
    int row0 = blockIdx.x * RPB;
    int tid = threadIdx.x;
    int wid = tid >> 5, lane = tid & 31;
    int j0 = tid * 4;
    int bL = b * LDIM;

    __shared__ __align__(16) char sbuf[NSTG * STAGE_BYTES];
    __shared__ float c_sh[LDIM];
    __shared__ float srow[8][RPB];

    // ---- prologue: Lm / c from S[t] (every block, redundant but cheap) ----
    {
        float4 rs = *(const float4*)&g_Srs[t][bL + j0];
        float4 cs = *(const float4*)&g_Scs[t][bL + j0];
        float4 lmp = make_float4(0.f, 0.f, 0.f, 0.f);
        if (t > 0) lmp = *(const float4*)&g_LmBuf[(t - 1) & 1][bL + j0];
        float wv = w_p[0];
        float bt = belt_p[0] * powf(lrb_p[0], (float)(t - 1));
        float4 lm;
#pragma unroll
        for (int k = 0; k < 4; k++) {
            float r = 0.5f * (((const float*)&rs)[k] + ((const float*)&cs)[k]) - 1.0f;
            float pr = fmaxf(r, 0.f);
            float l = (t == 0) ? (wv * pr) : (((const float*)&lmp)[k] + bt * pr);
            float sgn = (r > 0.f) ? 1.f : ((r < 0.f) ? -1.f : 0.f);
            ((float*)&lm)[k] = l;
            c_sh[j0 + k] = l * sgn;
        }
        if (blockIdx.x == 0) *(float4*)&g_LmBuf[t & 1][bL + j0] = lm;
    }

    const float* Ain = use_x ? x : (const float*)g_Ahat;
    float* Aout = g_Ahat;

    float at = alpha_p[0] * powf(lra_p[0], (float)t);

    size_t baseB = (size_t)b * LDIM * LDIM;
    size_t gbase0 = baseB + (size_t)row0 * LDIM + j0;   // A / M / Us base (row r: + r*LDIM)
    size_t rbase0 = (size_t)row0 * LDIM + j0;           // rho base

    // ---- issue helper (macro so smem offsets stay compile-time) ----
#define ISSUE_ROW(p)                                                          \
    do {                                                                      \
        char* st_ = sbuf + ((p) % NSTG) * STAGE_BYTES;                        \
        size_t g_ = gbase0 + (size_t)(p) * LDIM;                              \
        size_t rg_ = rbase0 + (size_t)(p) * LDIM;                             \
        __pipeline_memcpy_async(st_ + A_OFF + tid * 16, Ain + g_, 16);        \
        __pipeline_memcpy_async(st_ + R_OFF + tid * 16, rho + rg_, 16);       \
        __pipeline_memcpy_async(st_ + U_OFF + tid * 8,  g_Ush + g_, 8);       \
        __pipeline_memcpy_async(st_ + M_OFF + tid * 4,  g_M8 + g_, 4);        \
    } while (0)

    // prefetch rows 0..NSTG-2
#pragma unroll
    for (int p = 0; p < NSTG - 1; p++) {
        ISSUE_ROW(p);
        __pipeline_commit();
    }

    __syncthreads();   // c_sh ready (placed after prefetch issue to overlap)

    float4 cj = *(const float4*)&c_sh[j0];
    float ca0 = 0.f, ca1 = 0.f, ca2 = 0.f, ca3 = 0.f;

#pragma unroll
    for (int r = 0; r < RPB; r++) {
        if (r + NSTG - 1 < RPB) ISSUE_ROW(r + NSTG - 1);
        __pipeline_commit();
        __pipeline_wait_prior(NSTG - 1);

        const char* st = sbuf + (r % NSTG) * STAGE_BYTES;
        float4 ah = *(const float4*)(st + A_OFF + tid * 16);
        float4 rp = *(const float4*)(st + R_OFF + tid * 16);
        uint2 uu  = *(const uint2*)(st + U_OFF + tid * 8);
        unsigned int m_c = *(const unsigned int*)(st + M_OFF + tid * 4);
        float ci = c_sh[row0 + r];

        float2 us01 = __half22float2(*reinterpret_cast<__half2*>(&uu.x));
        float2 us23 = __half22float2(*reinterpret_cast<__half2*>(&uu.y));
        float m0 = (float)(m_c & 0xff), m1 = (float)((m_c >> 8) & 0xff);
        float m2 = (float)((m_c >> 16) & 0xff), m3 = (float)(m_c >> 24);

        float rowp = 0.f;
        float4 ov;
        {
            float g = us01.x - ci - cj.x;
            float v = ah.x + at * ah.x * m0 * g;
            float sv = fminf(fmaxf(fabsf(v) - rp.x * at, 0.f), 1.f);
            ov.x = sv; float am = sv * m0; rowp += am; ca0 += am;
        }
        {
            float g = us01.y - ci - cj.y;
            float v = ah.y + at * ah.y * m1 * g;
            float sv = fminf(fmaxf(fabsf(v) - rp.y * at, 0.f), 1.f);
            ov.y = sv; float am = sv * m1; rowp += am; ca1 += am;
        }
        {
            float g = us23.x - ci - cj.z;
            float v = ah.z + at * ah.z * m2 * g;
            float sv = fminf(fmaxf(fabsf(v) - rp.z * at, 0.f), 1.f);
            ov.z = sv; float am = sv * m2; rowp += am; ca2 += am;
        }
        {
            float g = us23.y - ci - cj.w;
            float v = ah.w + at * ah.w * m3 * g;
            float sv = fminf(fmaxf(fabsf(v) - rp.w * at, 0.f), 1.f);
            ov.w = sv; float am = sv * m3; rowp += am; ca3 += am;
        }
        *(float4*)(Aout + gbase0 + (size_t)r * LDIM) = ov;

#pragma unroll
        for (int o = 16; o > 0; o >>= 1) rowp += __shfl_down_sync(0xffffffffu, rowp, o);
        if (lane == 0) srow[wid][r] = rowp;
    }
#undef ISSUE_ROW

    __syncthreads();
    if (tid < RPB) {
        float s = 0.f;
#pragma unroll
        for (int w = 0; w < 8; w++) s += srow[w][tid];
        g_Srs[t + 1][bL + row0 + tid] = s;  // block covers full row: direct store
    }
    atomicAdd(&g_Scs[t + 1][bL + j0 + 0], ca0);
    atomicAdd(&g_Scs[t + 1][bL + j0 + 1], ca1);
    atomicAdd(&g_Scs[t + 1][bL + j0 + 2], ca2);
    atomicAdd(&g_Scs[t + 1][bL + j0 + 3], ca3);
}

// ---------------------------------------------------------------------------
// Final: out = 0.5*(Ahat + Ahat^T) .* M   (tiled transpose, u8 mask)
// ---------------------------------------------------------------------------
__global__ void final_kernel(float* __restrict__ out) {
    __shared__ float t2[32][33];
    int b = blockIdx.z;
    int tx = blockIdx.x, ty = blockIdx.y;
    int c = threadIdx.x;
    int r0 = threadIdx.y * 4;
    const float* ab = g_Ahat + (size_t)b * LDIM * LDIM;
    const unsigned char* mb = g_M8 + (size_t)b * LDIM * LDIM;
    float* ob = out + (size_t)b * LDIM * LDIM;

#pragma unroll
    for (int k = 0; k < 4; k++) {
        int r = r0 + k;
        t2[r][c] = ab[(size_t)(tx * 32 + r) * LDIM + ty * 32 + c];
    }
    __syncthreads();
#pragma unroll
    for (int k = 0; k < 4; k++) {
        int r = r0 + k;
        int gi = ty * 32 + r;
        int gj = tx * 32 + c;
        size_t idx = (size_t)gi * LDIM + gj;
        ob[idx] = 0.5f * (ab[idx] + t2[c][r]) * (float)mb[idx];
    }
}

// ---------------------------------------------------------------------------
extern "C" void kernel_launch(void* const* d_in, const int* in_sizes, int n_in,
                              void* d_out, int out_size) {
    const float* x     = (const float*)d_in[0];
    const float* M     = (const float*)d_in[1];
    const float* s_p   = (const float*)d_in[2];
    const float* w_p   = (const float*)d_in[3];
    const float* rho_p = (const float*)d_in[4];
    const float* alpha_p = (const float*)d_in[5];
    const float* belt_p  = (const float*)d_in[6];
    const float* lra_p   = (const float*)d_in[7];
    const float* lrb_p   = (const float*)d_in[8];
    float* out = (float*)d_out;

    // 1. zero all step-sum buffers
    int nz = (STEPS + 1) * BDIM * LDIM;
    zero_kernel<<<(nz + 255) / 256, 256>>>();

    // 2. init: Us(fp16), M8, S[0]
    dim3 tgrid(LDIM / 32, LDIM / 32, BDIM);
    dim3 tblk(32, 8);
    init_kernel<<<tgrid, tblk>>>(x, M, s_p);

    // 3. main loop (Lm/c fused into step prologue)
    dim3 sgrid(LDIM / RPB, BDIM);
    for (int t = 0; t < STEPS; t++) {
        step_kernel<<<sgrid, 256>>>(x, rho_p, w_p, alpha_p, belt_p, lra_p, lrb_p,
                                    t, t == 0 ? 1 : 0);
    }

    // 4. output symmetrize
    final_kernel<<<tgrid, tblk>>>(out);
}